// round 12
// baseline (speedup 1.0000x reference)
#include <cuda_runtime.h>
#include <cuda_bf16.h>
#include <cuda_fp16.h>
#include <cstdint>

#define B_   8
#define CIN  256
#define HW_  4096
#define DQK  16
#define NO_  288
#define L2E  1.4426950408889634f
#define PSHIFT 10.0f

typedef unsigned long long u64;

// ---------------- portable PTX helpers ----------------
__device__ __forceinline__ uint32_t smem_u32(const void* p) {
    uint32_t a;
    asm("{ .reg .u64 t; cvta.to.shared.u64 t, %1; cvt.u32.u64 %0, t; }" : "=r"(a) : "l"(p));
    return a;
}
__device__ __forceinline__ float ex2(float v) {
    float r; asm("ex2.approx.f32 %0, %1;" : "=f"(r) : "f"(v)); return r;
}
__device__ __forceinline__ uint32_t pack_h2(float lo, float hi) {
    uint32_t d; asm("cvt.rn.f16x2.f32 %0, %1, %2;" : "=r"(d) : "f"(hi), "f"(lo)); return d;
}
__device__ __forceinline__ uint32_t pack_b2(float lo, float hi) {
    uint32_t d; asm("cvt.rn.bf16x2.f32 %0, %1, %2;" : "=r"(d) : "f"(hi), "f"(lo)); return d;
}
__device__ __forceinline__ float bfv(float v) {
    __nv_bfloat16 h = __float2bfloat16(v);
    return __bfloat162float(h);
}
__device__ __forceinline__ uint32_t lds32(uint32_t a) {
    uint32_t v; asm volatile("ld.shared.b32 %0, [%1];" : "=r"(v) : "r"(a)); return v;
}
__device__ __forceinline__ void lds64(uint32_t& x, uint32_t& y, uint32_t a) {
    asm volatile("ld.shared.v2.b32 {%0, %1}, [%2];" : "=r"(x), "=r"(y) : "r"(a));
}
__device__ __forceinline__ void sts32(uint32_t a, uint32_t v) {
    asm volatile("st.shared.b32 [%0], %1;" :: "r"(a), "r"(v));
}
#define CP16(dst, src) asm volatile("cp.async.cg.shared.global [%0], [%1], 16;" :: "r"(dst), "l"(src))
#define CP_COMMIT()    asm volatile("cp.async.commit_group;" ::: "memory")
#define CP_WAIT0()     asm volatile("cp.async.wait_group 0;" ::: "memory")
#define CP_WAIT1()     asm volatile("cp.async.wait_group 1;" ::: "memory")

// bf16 m16n8k16 (fp32 accum)
__device__ __forceinline__ void mma_ba(float* d, const uint32_t* a, uint32_t b0, uint32_t b1) {
    asm volatile("mma.sync.aligned.m16n8k16.row.col.f32.bf16.bf16.f32 "
        "{%0,%1,%2,%3}, {%4,%5,%6,%7}, {%8,%9}, {%0,%1,%2,%3};"
        : "+f"(d[0]), "+f"(d[1]), "+f"(d[2]), "+f"(d[3])
        : "r"(a[0]), "r"(a[1]), "r"(a[2]), "r"(a[3]), "r"(b0), "r"(b1));
}
__device__ __forceinline__ void mma_bz(float* d, const uint32_t* a, uint32_t b0, uint32_t b1) {
    float z = 0.f;
    asm volatile("mma.sync.aligned.m16n8k16.row.col.f32.bf16.bf16.f32 "
        "{%0,%1,%2,%3}, {%4,%5,%6,%7}, {%8,%9}, {%10,%10,%10,%10};"
        : "=f"(d[0]), "=f"(d[1]), "=f"(d[2]), "=f"(d[3])
        : "r"(a[0]), "r"(a[1]), "r"(a[2]), "r"(a[3]), "r"(b0), "r"(b1), "f"(z));
}
// fp16 m16n8k16 (fp32 accum)
__device__ __forceinline__ void mma_h16(float* d, const uint32_t* a, uint32_t b0, uint32_t b1) {
    asm volatile("mma.sync.aligned.m16n8k16.row.col.f32.f16.f16.f32 "
        "{%0,%1,%2,%3}, {%4,%5,%6,%7}, {%8,%9}, {%0,%1,%2,%3};"
        : "+f"(d[0]), "+f"(d[1]), "+f"(d[2]), "+f"(d[3])
        : "r"(a[0]), "r"(a[1]), "r"(a[2]), "r"(a[3]), "r"(b0), "r"(b1));
}

// key permutation within 16-groups (pairs stay adjacent)
__device__ __forceinline__ int kperm(int e) {
    return (((e & 7) >> 1) << 2) | (e & 1) | ((e >> 3) << 1);
}

// ---------------- scratch ----------------
__device__ float         d_gbuf[B_ * DQK * HW_];
__device__ __nv_bfloat16 d_fkm[(size_t)B_ * HW_ * 32];   // F key-major: 16 hi + 16 lo bf16
__device__ __half        d_hh[(size_t)B_ * CIN * HW_];   // V fp16, key-permuted within 16-groups
__device__ __nv_bfloat16 d_xt[(size_t)B_ * HW_ * 512];   // x pixel-major: [b][px][plane][c]
__device__ __nv_bfloat16 d_wt[NO_ * 512];                // W: [o][plane][c]
__device__ float         d_ball[NO_];

// ---------------- prep ----------------
__global__ void prep_kernel(const float* __restrict__ Wf, const float* __restrict__ bf,
                            const float* __restrict__ Wg, const float* __restrict__ bg,
                            const float* __restrict__ Wh, const float* __restrict__ bh) {
    int i = blockIdx.x * blockDim.x + threadIdx.x;
    if (i >= NO_ * CIN) return;
    int o = i >> 8, c = i & 255;
    float w = (o < 16) ? Wf[o * 256 + c] : ((o < 32) ? Wg[(o - 16) * 256 + c] : Wh[(o - 32) * 256 + c]);
    float h = bfv(w);
    d_wt[o * 512 + c]       = __float2bfloat16(h);
    d_wt[o * 512 + 256 + c] = __float2bfloat16(w - h);
    if (c == 0) d_ball[o] = (o < 16) ? bf[o] : ((o < 32) ? bg[o - 16] : bh[o - 32]);
}

// ---------------- xconv ----------------
__global__ __launch_bounds__(256) void xconv_kernel(const float* __restrict__ x) {
    __shared__ float tx[32][65];
    const int px0 = blockIdx.x * 64;
    const int c0  = blockIdx.y * 32;
    const int b   = blockIdx.z;
    const int tid = threadIdx.x;
    const float* xb = x + (size_t)b * CIN * HW_;
#pragma unroll
    for (int it = 0; it < 8; it++) {
        int e = tid + 256 * it;
        int c = e >> 6, p = e & 63;
        tx[c][p] = xb[(size_t)(c0 + c) * HW_ + px0 + p];
    }
    __syncthreads();
    uint32_t* dst = (uint32_t*)d_xt;
#pragma unroll
    for (int it = 0; it < 8; it++) {
        int e = tid + 256 * it;
        int px = e >> 5, q = e & 31;
        int plane = q >> 4, cp = q & 15;
        float v0 = tx[2 * cp][px], v1 = tx[2 * cp + 1][px];
        float h0 = bfv(v0), h1 = bfv(v1);
        uint32_t outw = plane ? pack_b2(v0 - h0, v1 - h1) : pack_b2(h0, h1);
        size_t idx = (((size_t)b * HW_ + px0 + px) * 512 + plane * 256 + c0 + 2 * cp) >> 1;
        dst[idx] = outw;
    }
}

// ---------------- proj GEMM on tensor cores (bf16 x3) ----------------
#define PX_STRIDE 144
#define PW_STRIDE 144
#define PX_SZ     (128 * PX_STRIDE)
#define PW_OFF    (2 * PX_SZ)
#define PW_SZ     (288 * PW_STRIDE)
#define PROJ_SMEM (PW_OFF + 2 * PW_SZ)

__device__ __forceinline__ void proj_load(uint32_t sb, int slot, int b, int px0, int kc, int tid) {
    uint32_t xdst = sb + slot * PX_SZ;
    const __nv_bfloat16* xsrc = d_xt + ((size_t)b * HW_ + px0) * 512 + kc;
#pragma unroll
    for (int j = 0; j < 4; j++) {
        int e = tid * 4 + j;
        int px = e >> 3, sub = e & 7;
        int pl = sub >> 2, c16 = sub & 3;
        CP16(xdst + px * PX_STRIDE + pl * 64 + c16 * 16, xsrc + (size_t)px * 512 + pl * 256 + c16 * 8);
    }
    uint32_t wdst = sb + PW_OFF + slot * PW_SZ;
    const __nv_bfloat16* wsrc = d_wt + kc;
#pragma unroll
    for (int it = 0; it < 9; it++) {
        int e = tid + 256 * it;
        int o = e >> 3, sub = e & 7;
        int pl = sub >> 2, c16 = sub & 3;
        CP16(wdst + o * PW_STRIDE + pl * 64 + c16 * 16, wsrc + (size_t)o * 512 + pl * 256 + c16 * 8);
    }
    CP_COMMIT();
}

__global__ __launch_bounds__(256, 1) void proj_mma_kernel() {
    extern __shared__ char smraw[];
    const uint32_t sb = smem_u32(smraw);
    const int tid = threadIdx.x, wid = tid >> 5, lane = tid & 31;
    const int t4 = lane & 3, r4 = lane >> 2;
    const int oh = wid & 1, pq = wid >> 1;
    const int px0 = blockIdx.x * 128;
    const int b = blockIdx.y;

    float acc[9][4][4];
#pragma unroll
    for (int mt = 0; mt < 9; mt++)
#pragma unroll
        for (int nt = 0; nt < 4; nt++) { acc[mt][nt][0] = acc[mt][nt][1] = acc[mt][nt][2] = acc[mt][nt][3] = 0.f; }

    proj_load(sb, 0, b, px0, 0, tid);

    for (int ch = 0; ch < 8; ch++) {
        CP_WAIT0();
        __syncthreads();
        if (ch + 1 < 8) proj_load(sb, (ch + 1) & 1, b, px0, (ch + 1) * 32, tid);

        const uint32_t xs = sb + (ch & 1) * PX_SZ;
        const uint32_t ws = sb + PW_OFF + (ch & 1) * PW_SZ;
#pragma unroll
        for (int ks = 0; ks < 2; ks++) {
            uint32_t bh[4][2], bl[4][2];
#pragma unroll
            for (int nt = 0; nt < 4; nt++) {
                uint32_t base = xs + (pq * 32 + nt * 8 + r4) * PX_STRIDE + ks * 32 + t4 * 4;
                bh[nt][0] = lds32(base);       bh[nt][1] = lds32(base + 16);
                bl[nt][0] = lds32(base + 64);  bl[nt][1] = lds32(base + 80);
            }
#pragma unroll
            for (int mt = 0; mt < 9; mt++) {
                uint32_t base = ws + (oh * 144 + mt * 16 + r4) * PW_STRIDE + ks * 32 + t4 * 4;
                uint32_t Ah[4], Al[4];
                Ah[0] = lds32(base);                 Ah[1] = lds32(base + 8 * PW_STRIDE);
                Ah[2] = lds32(base + 16);            Ah[3] = lds32(base + 8 * PW_STRIDE + 16);
                Al[0] = lds32(base + 64);            Al[1] = lds32(base + 8 * PW_STRIDE + 64);
                Al[2] = lds32(base + 80);            Al[3] = lds32(base + 8 * PW_STRIDE + 80);
#pragma unroll
                for (int nt = 0; nt < 4; nt++) {
                    mma_ba(acc[mt][nt], Ah, bh[nt][0], bh[nt][1]);
                    mma_ba(acc[mt][nt], Al, bh[nt][0], bh[nt][1]);
                    mma_ba(acc[mt][nt], Ah, bl[nt][0], bl[nt][1]);
                }
            }
        }
        __syncthreads();
    }

#pragma unroll
    for (int mt = 0; mt < 9; mt++) {
#pragma unroll
        for (int nt = 0; nt < 4; nt++) {
            int px = pq * 32 + nt * 8 + 2 * t4;
#pragma unroll
            for (int r = 0; r < 2; r++) {
                int o = oh * 144 + mt * 16 + r4 + 8 * r;
                float bias = d_ball[o];
                float va = acc[mt][nt][2 * r]     + bias;
                float vb = acc[mt][nt][2 * r + 1] + bias;
                if (oh == 0 && mt == 0) {
                    size_t base = ((size_t)b * HW_ + px0 + px) * 32;
                    float ha = bfv(va), hb = bfv(vb);
                    d_fkm[base + o]      = __float2bfloat16(ha);
                    d_fkm[base + 16 + o] = __float2bfloat16(va - ha);
                    d_fkm[base + 32 + o] = __float2bfloat16(hb);
                    d_fkm[base + 48 + o] = __float2bfloat16(vb - hb);
                } else if (oh == 0 && mt == 1) {
                    float2 st; st.x = va; st.y = vb;
                    *(float2*)&d_gbuf[((size_t)b * DQK + (o - 16)) * HW_ + px0 + px] = st;
                } else {
                    int c = o - 32;
                    int pxp = (px & ~15) | kperm(px & 15);
                    *(uint32_t*)&d_hh[((size_t)b * CIN + c) * HW_ + px0 + pxp] = pack_h2(va, vb);
                }
            }
        }
    }
}

// ---------------- attention: 64-query CTAs, 512 threads, 2 CTAs/SM ----------------
// 16 warps = 2 qgroups(32q) x 8 subs. QK: 8 keys/warp. PV: 32 channels/warp.
#define FROW 80
#define FSZ  5120
#define VROW 160
#define VSZ  40960
#define PROW 160
#define PSZ  10240
#define OFF_F 0
#define OFF_V 10240
#define OFF_P 92160
#define OFF_RS 112640
#define SMEM_BYTES 114688

// combined F(fi)+V(vi) load, one commit group
__device__ __forceinline__ void load_fv(uint32_t sb, int fi, int vi,
                                        const __nv_bfloat16* fkm, const __half* vb, int tid) {
    if (fi >= 0 && fi < 64 && tid < 256) {
        int key = tid >> 2, g = tid & 3;
        CP16(sb + OFF_F + (fi & 1) * FSZ + key * FROW + g * 16,
             fkm + (size_t)(fi * 64 + key) * 32 + g * 8);
    }
    if (vi >= 0 && vi < 64) {
        uint32_t vdst = sb + OFF_V + (vi & 1) * VSZ;
#pragma unroll
        for (int j = 0; j < 4; j++) {
            int e = tid + 512 * j;
            int row = e >> 3, c = e & 7;
            CP16(vdst + row * VROW + c * 16, vb + (size_t)row * HW_ + vi * 64 + c * 8);
        }
    }
    CP_COMMIT();
}

// prepass F-only load into the V region (3 slots)
__device__ __forceinline__ void load_fp(uint32_t sb, int slot, const __nv_bfloat16* fkm,
                                        int m0, int tid) {
    if (tid < 128) {
        int key = tid >> 1, g = tid & 1;
        CP16(sb + OFF_V + slot * FSZ + key * FROW + g * 16, fkm + (size_t)(m0 + key) * 32 + g * 8);
    }
    CP_COMMIT();
}

// QK (bf16 x3, 8 keys) + softmax + P store (kperm-matched)
__device__ __forceinline__ void qk_tile(uint32_t sb, int fslot, int pslot,
                                        const uint32_t qh[2][4], const uint32_t ql[2][4],
                                        const float negml[2][2], float rs[2][2],
                                        int qg, int sub, int t4, int r4) {
    const uint32_t fb_ = sb + OFF_F + fslot * FSZ + (sub * 8 + r4) * FROW + t4 * 4;
    uint32_t bh0 = lds32(fb_), bh1 = lds32(fb_ + 16);
    uint32_t bl0 = lds32(fb_ + 32), bl1 = lds32(fb_ + 48);
    float s0[4], s1[4];
    mma_bz(s0, qh[0], bh0, bh1);
    mma_bz(s1, qh[1], bh0, bh1);
    mma_ba(s0, ql[0], bh0, bh1);
    mma_ba(s1, ql[1], bh0, bh1);
    mma_ba(s0, qh[0], bl0, bl1);
    mma_ba(s1, qh[1], bl0, bl1);

    const uint32_t pbase = sb + OFF_P + pslot * PSZ + (qg * 32) * PROW;
    const uint32_t poff = (uint32_t)((sub >> 1) * 32 + t4 * 8 + (sub & 1) * 4);
#pragma unroll
    for (int qt = 0; qt < 2; qt++) {
        const float* s = qt ? s1 : s0;
        uint32_t prow = pbase + (qt * 16 + r4) * PROW;
        float p0 = ex2(fmaf(s[0], L2E, negml[qt][0]));
        float p1 = ex2(fmaf(s[1], L2E, negml[qt][0]));
        float p2 = ex2(fmaf(s[2], L2E, negml[qt][1]));
        float p3 = ex2(fmaf(s[3], L2E, negml[qt][1]));
        rs[qt][0] += p0 + p1;
        rs[qt][1] += p2 + p3;
        sts32(prow + poff, pack_h2(p0, p1));
        sts32(prow + 8 * PROW + poff, pack_h2(p2, p3));
    }
}

// PV (fp16): 32 queries x 32 channels per warp
__device__ __forceinline__ void pv_tile(uint32_t sb, int vslot, int pslot,
                                        float acc0[4][4], float acc1[4][4],
                                        int qg, int sub, int t4, int r4) {
    const uint32_t pb = sb + OFF_P + pslot * PSZ + (qg * 32) * PROW;
    const uint32_t vrow = sb + OFF_V + vslot * VSZ + (sub * 32 + r4) * VROW + t4 * 8;
#pragma unroll
    for (int ks = 0; ks < 4; ks++) {
        uint32_t A0[4], A1[4];
        uint32_t pr = pb + r4 * PROW + ks * 32 + t4 * 8;
        lds64(A0[0], A0[2], pr);
        lds64(A0[1], A0[3], pr + 8 * PROW);
        lds64(A1[0], A1[2], pr + 16 * PROW);
        lds64(A1[1], A1[3], pr + 24 * PROW);
        const uint32_t vk = vrow + ks * 32;
#pragma unroll
        for (int ct = 0; ct < 4; ct++) {
            uint32_t b0, b1;
            lds64(b0, b1, vk + ct * 8 * VROW);
            mma_h16(acc0[ct], A0, b0, b1);
            mma_h16(acc1[ct], A1, b0, b1);
        }
    }
}

__global__ __launch_bounds__(512, 2) void attn_kernel(const float* __restrict__ x,
                                                      const float* __restrict__ gamma_p,
                                                      float* __restrict__ out) {
    extern __shared__ char smraw[];
    const uint32_t sb = smem_u32(smraw);
    float* rsm = (float*)(smraw + OFF_RS);
    const int tid = threadIdx.x, wid = tid >> 5, lane = tid & 31;
    const int t4 = lane & 3, r4 = lane >> 2;
    const int qg = wid >> 3, sub = wid & 7;
    const int b = blockIdx.y, n0 = blockIdx.x * 64;

    const float*         gb  = d_gbuf + (size_t)b * DQK * HW_;
    const __nv_bfloat16* fkm = d_fkm + (size_t)b * HW_ * 32;
    const __half*        vbp = d_hh  + (size_t)b * CIN * HW_;

    // ---- Q fragments: bf16 hi/lo ----
    uint32_t qh[2][4], ql[2][4];
#pragma unroll
    for (int qt = 0; qt < 2; qt++) {
        const int nq = n0 + qg * 32 + qt * 16 + r4;
#pragma unroll
        for (int h = 0; h < 2; h++) {
            int k0 = 2 * t4 + 8 * h;
            float va0 = gb[(size_t)k0 * HW_ + nq];
            float va1 = gb[(size_t)(k0 + 1) * HW_ + nq];
            float vb0 = gb[(size_t)k0 * HW_ + nq + 8];
            float vb1 = gb[(size_t)(k0 + 1) * HW_ + nq + 8];
            float ha0 = bfv(va0), ha1 = bfv(va1), hb0 = bfv(vb0), hb1 = bfv(vb1);
            qh[qt][2 * h]     = pack_b2(ha0, ha1);
            qh[qt][2 * h + 1] = pack_b2(hb0, hb1);
            ql[qt][2 * h]     = pack_b2(va0 - ha0, va1 - ha1);
            ql[qt][2 * h + 1] = pack_b2(vb0 - hb0, vb1 - hb1);
        }
    }

    // ================= PREPASS: exact per-row max (bf16 hi, 8 keys/warp) =================
    // Pipeline invariant: the slot being read is NEVER the most-recent commit group.
    // Iterations that have no prefetch still issue an EMPTY commit so CP_WAIT1 keeps
    // the invariant at the tail (round-11 inf bug: tile 63 was the newest group).
    float smax[2][2] = {{-1e30f, -1e30f}, {-1e30f, -1e30f}};
    load_fp(sb, 0, fkm, 0, tid);
    load_fp(sb, 1, fkm, 64, tid);
    for (int i = 0; i < 64; i++) {
        CP_WAIT1();
        __syncthreads();
        if (i + 2 < 64) load_fp(sb, (i + 2) % 3, fkm, (i + 2) * 64, tid);
        else            CP_COMMIT();   // keep group-count invariant at the tail
        const uint32_t fb_ = sb + OFF_V + (i % 3) * FSZ + (sub * 8 + r4) * FROW + t4 * 4;
        uint32_t b0 = lds32(fb_), b1 = lds32(fb_ + 16);
        float s0[4], s1[4];
        mma_bz(s0, qh[0], b0, b1);
        mma_bz(s1, qh[1], b0, b1);
        smax[0][0] = fmaxf(smax[0][0], fmaxf(s0[0], s0[1]));
        smax[0][1] = fmaxf(smax[0][1], fmaxf(s0[2], s0[3]));
        smax[1][0] = fmaxf(smax[1][0], fmaxf(s1[0], s1[1]));
        smax[1][1] = fmaxf(smax[1][1], fmaxf(s1[2], s1[3]));
    }
    CP_WAIT0();
#pragma unroll
    for (int qt = 0; qt < 2; qt++)
#pragma unroll
        for (int j = 0; j < 2; j++) {
            float m = smax[qt][j];
            m = fmaxf(m, __shfl_xor_sync(0xffffffffu, m, 1));
            m = fmaxf(m, __shfl_xor_sync(0xffffffffu, m, 2));
            smax[qt][j] = m;
        }
    __syncthreads();
    if (t4 == 0) {
#pragma unroll
        for (int qt = 0; qt < 2; qt++) {
            rsm[sub * 64 + qg * 32 + qt * 16 + r4]     = smax[qt][0];
            rsm[sub * 64 + qg * 32 + qt * 16 + r4 + 8] = smax[qt][1];
        }
    }
    __syncthreads();
    float negml[2][2];
#pragma unroll
    for (int qt = 0; qt < 2; qt++) {
#pragma unroll
        for (int j = 0; j < 2; j++) {
            int row = qg * 32 + qt * 16 + r4 + 8 * j;
            float m = rsm[row];
#pragma unroll
            for (int ss = 1; ss < 8; ss++) m = fmaxf(m, rsm[ss * 64 + row]);
            negml[qt][j] = PSHIFT - m * L2E;
        }
    }
    __syncthreads();   // rsm free for reuse; prepass F slots free

    // ================= MAIN LOOP =================
    float acc0[4][4], acc1[4][4];
#pragma unroll
    for (int ct = 0; ct < 4; ct++) {
        acc0[ct][0] = acc0[ct][1] = acc0[ct][2] = acc0[ct][3] = 0.f;
        acc1[ct][0] = acc1[ct][1] = acc1[ct][2] = acc1[ct][3] = 0.f;
    }
    float rs[2][2] = {{0.f, 0.f}, {0.f, 0.f}};

    load_fv(sb, 0, -1, fkm, vbp, tid);
    load_fv(sb, 1, 0, fkm, vbp, tid);
    CP_WAIT0();
    __syncthreads();
    qk_tile(sb, 0, 0, qh, ql, negml, rs, qg, sub, t4, r4);   // P(0)

    for (int i = 0; i < 64; i++) {
        CP_WAIT0();
        __syncthreads();   // P(i) visible; F(i+1),V(i) loaded; stale slots free
        load_fv(sb, i + 2, i + 1, fkm, vbp, tid);
        if (i + 1 < 64) qk_tile(sb, (i + 1) & 1, (i + 1) & 1, qh, ql, negml, rs, qg, sub, t4, r4);
        pv_tile(sb, i & 1, i & 1, acc0, acc1, qg, sub, t4, r4);
    }

    // ---- combine row sums across the eight key-subs ----
    __syncthreads();
#pragma unroll
    for (int qt = 0; qt < 2; qt++) {
        float r0 = rs[qt][0], r1 = rs[qt][1];
        r0 += __shfl_xor_sync(0xffffffffu, r0, 1); r0 += __shfl_xor_sync(0xffffffffu, r0, 2);
        r1 += __shfl_xor_sync(0xffffffffu, r1, 1); r1 += __shfl_xor_sync(0xffffffffu, r1, 2);
        if (t4 == 0) {
            rsm[sub * 64 + qg * 32 + qt * 16 + r4]     = r0;
            rsm[sub * 64 + qg * 32 + qt * 16 + r4 + 8] = r1;
        }
    }
    __syncthreads();

    // ---- epilogue ----
    const float gm = *gamma_p;
    const float* xb = x + (size_t)b * CIN * HW_;
    float* ob = out + (size_t)b * CIN * HW_;
#pragma unroll
    for (int qt = 0; qt < 2; qt++) {
        float (*acc)[4] = qt ? acc1 : acc0;
        int ra = qg * 32 + qt * 16 + r4, rb = ra + 8;
        float suma = 0.f, sumb = 0.f;
#pragma unroll
        for (int ss = 0; ss < 8; ss++) { suma += rsm[ss * 64 + ra]; sumb += rsm[ss * 64 + rb]; }
        float inva = gm / suma;
        float invb = gm / sumb;
        int na = n0 + ra, nb = n0 + rb;
#pragma unroll
        for (int ct = 0; ct < 4; ct++) {
            int ch0 = sub * 32 + ct * 8 + 2 * t4, ch1 = ch0 + 1;
            ob[(size_t)ch0 * HW_ + na] = fmaf(inva, acc[ct][0], xb[(size_t)ch0 * HW_ + na]);
            ob[(size_t)ch1 * HW_ + na] = fmaf(inva, acc[ct][1], xb[(size_t)ch1 * HW_ + na]);
            ob[(size_t)ch0 * HW_ + nb] = fmaf(invb, acc[ct][2], xb[(size_t)ch0 * HW_ + nb]);
            ob[(size_t)ch1 * HW_ + nb] = fmaf(invb, acc[ct][3], xb[(size_t)ch1 * HW_ + nb]);
        }
    }
}

// ---------------- launch ----------------
extern "C" void kernel_launch(void* const* d_in, const int* in_sizes, int n_in,
                              void* d_out, int out_size) {
    const float* x  = (const float*)d_in[0];
    const float* Wf = (const float*)d_in[1];
    const float* bf = (const float*)d_in[2];
    const float* Wg = (const float*)d_in[3];
    const float* bg = (const float*)d_in[4];
    const float* Wh = (const float*)d_in[5];
    const float* bh = (const float*)d_in[6];
    const float* gamma = (const float*)d_in[7];
    float* out = (float*)d_out;

    prep_kernel<<<(NO_ * CIN + 255) / 256, 256>>>(Wf, bf, Wg, bg, Wh, bh);
    xconv_kernel<<<dim3(HW_ / 64, CIN / 32, B_), 256>>>(x);

    cudaFuncSetAttribute(proj_mma_kernel, cudaFuncAttributeMaxDynamicSharedMemorySize, PROJ_SMEM);
    proj_mma_kernel<<<dim3(HW_ / 128, B_), 256, PROJ_SMEM>>>();

    cudaFuncSetAttribute(attn_kernel, cudaFuncAttributeMaxDynamicSharedMemorySize, SMEM_BYTES);
    attn_kernel<<<dim3(HW_ / 64, B_), 512, SMEM_BYTES>>>(x, gamma, out);
}

// round 13
// speedup vs baseline: 1.6449x; 1.6449x over previous
#include <cuda_runtime.h>
#include <cuda_bf16.h>
#include <cuda_fp16.h>
#include <cstdint>

#define B_   8
#define CIN  256
#define HW_  4096
#define DQK  16
#define NO_  288
#define L2E  1.4426950408889634f
#define PSHIFT 10.0f

typedef unsigned long long u64;

// ---------------- portable PTX helpers ----------------
__device__ __forceinline__ uint32_t smem_u32(const void* p) {
    uint32_t a;
    asm("{ .reg .u64 t; cvta.to.shared.u64 t, %1; cvt.u32.u64 %0, t; }" : "=r"(a) : "l"(p));
    return a;
}
__device__ __forceinline__ float ex2(float v) {
    float r; asm("ex2.approx.f32 %0, %1;" : "=f"(r) : "f"(v)); return r;
}
__device__ __forceinline__ uint32_t pack_h2(float lo, float hi) {
    uint32_t d; asm("cvt.rn.f16x2.f32 %0, %1, %2;" : "=r"(d) : "f"(hi), "f"(lo)); return d;
}
__device__ __forceinline__ uint32_t pack_b2(float lo, float hi) {
    uint32_t d; asm("cvt.rn.bf16x2.f32 %0, %1, %2;" : "=r"(d) : "f"(hi), "f"(lo)); return d;
}
__device__ __forceinline__ float bfv(float v) {
    __nv_bfloat16 h = __float2bfloat16(v);
    return __bfloat162float(h);
}
__device__ __forceinline__ uint32_t lds32(uint32_t a) {
    uint32_t v; asm volatile("ld.shared.b32 %0, [%1];" : "=r"(v) : "r"(a)); return v;
}
__device__ __forceinline__ void lds64(uint32_t& x, uint32_t& y, uint32_t a) {
    asm volatile("ld.shared.v2.b32 {%0, %1}, [%2];" : "=r"(x), "=r"(y) : "r"(a));
}
__device__ __forceinline__ void sts32(uint32_t a, uint32_t v) {
    asm volatile("st.shared.b32 [%0], %1;" :: "r"(a), "r"(v));
}
#define CP16(dst, src) asm volatile("cp.async.cg.shared.global [%0], [%1], 16;" :: "r"(dst), "l"(src))
#define CP_COMMIT()    asm volatile("cp.async.commit_group;" ::: "memory")
#define CP_WAIT0()     asm volatile("cp.async.wait_group 0;" ::: "memory")
#define CP_WAIT1()     asm volatile("cp.async.wait_group 1;" ::: "memory")
#define CP_WAIT2()     asm volatile("cp.async.wait_group 2;" ::: "memory")

// bf16 m16n8k16 (fp32 accum)
__device__ __forceinline__ void mma_ba(float* d, const uint32_t* a, uint32_t b0, uint32_t b1) {
    asm volatile("mma.sync.aligned.m16n8k16.row.col.f32.bf16.bf16.f32 "
        "{%0,%1,%2,%3}, {%4,%5,%6,%7}, {%8,%9}, {%0,%1,%2,%3};"
        : "+f"(d[0]), "+f"(d[1]), "+f"(d[2]), "+f"(d[3])
        : "r"(a[0]), "r"(a[1]), "r"(a[2]), "r"(a[3]), "r"(b0), "r"(b1));
}
__device__ __forceinline__ void mma_bz(float* d, const uint32_t* a, uint32_t b0, uint32_t b1) {
    float z = 0.f;
    asm volatile("mma.sync.aligned.m16n8k16.row.col.f32.bf16.bf16.f32 "
        "{%0,%1,%2,%3}, {%4,%5,%6,%7}, {%8,%9}, {%10,%10,%10,%10};"
        : "=f"(d[0]), "=f"(d[1]), "=f"(d[2]), "=f"(d[3])
        : "r"(a[0]), "r"(a[1]), "r"(a[2]), "r"(a[3]), "r"(b0), "r"(b1), "f"(z));
}
// fp16 m16n8k16 (fp32 accum)
__device__ __forceinline__ void mma_h16(float* d, const uint32_t* a, uint32_t b0, uint32_t b1) {
    asm volatile("mma.sync.aligned.m16n8k16.row.col.f32.f16.f16.f32 "
        "{%0,%1,%2,%3}, {%4,%5,%6,%7}, {%8,%9}, {%0,%1,%2,%3};"
        : "+f"(d[0]), "+f"(d[1]), "+f"(d[2]), "+f"(d[3])
        : "r"(a[0]), "r"(a[1]), "r"(a[2]), "r"(a[3]), "r"(b0), "r"(b1));
}

// key permutation within 16-groups (pairs stay adjacent)
__device__ __forceinline__ int kperm(int e) {
    return (((e & 7) >> 1) << 2) | (e & 1) | ((e >> 3) << 1);
}

// ---------------- scratch ----------------
__device__ float         d_gbuf[B_ * DQK * HW_];
__device__ __nv_bfloat16 d_fkm[(size_t)B_ * HW_ * 32];   // F key-major: 16 hi + 16 lo bf16
__device__ __half        d_hh[(size_t)B_ * CIN * HW_];   // V fp16, key-permuted within 16-groups
__device__ __nv_bfloat16 d_xt[(size_t)B_ * HW_ * 512];   // x pixel-major: [b][px][plane][c]
__device__ __nv_bfloat16 d_wt[NO_ * 512];                // W: [o][plane][c]
__device__ float         d_ball[NO_];

// ---------------- prep ----------------
__global__ void prep_kernel(const float* __restrict__ Wf, const float* __restrict__ bf,
                            const float* __restrict__ Wg, const float* __restrict__ bg,
                            const float* __restrict__ Wh, const float* __restrict__ bh) {
    int i = blockIdx.x * blockDim.x + threadIdx.x;
    if (i >= NO_ * CIN) return;
    int o = i >> 8, c = i & 255;
    float w = (o < 16) ? Wf[o * 256 + c] : ((o < 32) ? Wg[(o - 16) * 256 + c] : Wh[(o - 32) * 256 + c]);
    float h = bfv(w);
    d_wt[o * 512 + c]       = __float2bfloat16(h);
    d_wt[o * 512 + 256 + c] = __float2bfloat16(w - h);
    if (c == 0) d_ball[o] = (o < 16) ? bf[o] : ((o < 32) ? bg[o - 16] : bh[o - 32]);
}

// ---------------- xconv ----------------
__global__ __launch_bounds__(256) void xconv_kernel(const float* __restrict__ x) {
    __shared__ float tx[32][65];
    const int px0 = blockIdx.x * 64;
    const int c0  = blockIdx.y * 32;
    const int b   = blockIdx.z;
    const int tid = threadIdx.x;
    const float* xb = x + (size_t)b * CIN * HW_;
#pragma unroll
    for (int it = 0; it < 8; it++) {
        int e = tid + 256 * it;
        int c = e >> 6, p = e & 63;
        tx[c][p] = xb[(size_t)(c0 + c) * HW_ + px0 + p];
    }
    __syncthreads();
    uint32_t* dst = (uint32_t*)d_xt;
#pragma unroll
    for (int it = 0; it < 8; it++) {
        int e = tid + 256 * it;
        int px = e >> 5, q = e & 31;
        int plane = q >> 4, cp = q & 15;
        float v0 = tx[2 * cp][px], v1 = tx[2 * cp + 1][px];
        float h0 = bfv(v0), h1 = bfv(v1);
        uint32_t outw = plane ? pack_b2(v0 - h0, v1 - h1) : pack_b2(h0, h1);
        size_t idx = (((size_t)b * HW_ + px0 + px) * 512 + plane * 256 + c0 + 2 * cp) >> 1;
        dst[idx] = outw;
    }
}

// ---------------- proj GEMM on tensor cores (bf16 x3) ----------------
#define PX_STRIDE 144
#define PW_STRIDE 144
#define PX_SZ     (128 * PX_STRIDE)
#define PW_OFF    (2 * PX_SZ)
#define PW_SZ     (288 * PW_STRIDE)
#define PROJ_SMEM (PW_OFF + 2 * PW_SZ)

__device__ __forceinline__ void proj_load(uint32_t sb, int slot, int b, int px0, int kc, int tid) {
    uint32_t xdst = sb + slot * PX_SZ;
    const __nv_bfloat16* xsrc = d_xt + ((size_t)b * HW_ + px0) * 512 + kc;
#pragma unroll
    for (int j = 0; j < 4; j++) {
        int e = tid * 4 + j;
        int px = e >> 3, sub = e & 7;
        int pl = sub >> 2, c16 = sub & 3;
        CP16(xdst + px * PX_STRIDE + pl * 64 + c16 * 16, xsrc + (size_t)px * 512 + pl * 256 + c16 * 8);
    }
    uint32_t wdst = sb + PW_OFF + slot * PW_SZ;
    const __nv_bfloat16* wsrc = d_wt + kc;
#pragma unroll
    for (int it = 0; it < 9; it++) {
        int e = tid + 256 * it;
        int o = e >> 3, sub = e & 7;
        int pl = sub >> 2, c16 = sub & 3;
        CP16(wdst + o * PW_STRIDE + pl * 64 + c16 * 16, wsrc + (size_t)o * 512 + pl * 256 + c16 * 8);
    }
    CP_COMMIT();
}

__global__ __launch_bounds__(256, 1) void proj_mma_kernel() {
    extern __shared__ char smraw[];
    const uint32_t sb = smem_u32(smraw);
    const int tid = threadIdx.x, wid = tid >> 5, lane = tid & 31;
    const int t4 = lane & 3, r4 = lane >> 2;
    const int oh = wid & 1, pq = wid >> 1;
    const int px0 = blockIdx.x * 128;
    const int b = blockIdx.y;

    float acc[9][4][4];
#pragma unroll
    for (int mt = 0; mt < 9; mt++)
#pragma unroll
        for (int nt = 0; nt < 4; nt++) { acc[mt][nt][0] = acc[mt][nt][1] = acc[mt][nt][2] = acc[mt][nt][3] = 0.f; }

    proj_load(sb, 0, b, px0, 0, tid);

    for (int ch = 0; ch < 8; ch++) {
        CP_WAIT0();
        __syncthreads();
        if (ch + 1 < 8) proj_load(sb, (ch + 1) & 1, b, px0, (ch + 1) * 32, tid);

        const uint32_t xs = sb + (ch & 1) * PX_SZ;
        const uint32_t ws = sb + PW_OFF + (ch & 1) * PW_SZ;
#pragma unroll
        for (int ks = 0; ks < 2; ks++) {
            uint32_t bh[4][2], bl[4][2];
#pragma unroll
            for (int nt = 0; nt < 4; nt++) {
                uint32_t base = xs + (pq * 32 + nt * 8 + r4) * PX_STRIDE + ks * 32 + t4 * 4;
                bh[nt][0] = lds32(base);       bh[nt][1] = lds32(base + 16);
                bl[nt][0] = lds32(base + 64);  bl[nt][1] = lds32(base + 80);
            }
#pragma unroll
            for (int mt = 0; mt < 9; mt++) {
                uint32_t base = ws + (oh * 144 + mt * 16 + r4) * PW_STRIDE + ks * 32 + t4 * 4;
                uint32_t Ah[4], Al[4];
                Ah[0] = lds32(base);                 Ah[1] = lds32(base + 8 * PW_STRIDE);
                Ah[2] = lds32(base + 16);            Ah[3] = lds32(base + 8 * PW_STRIDE + 16);
                Al[0] = lds32(base + 64);            Al[1] = lds32(base + 8 * PW_STRIDE + 64);
                Al[2] = lds32(base + 80);            Al[3] = lds32(base + 8 * PW_STRIDE + 80);
#pragma unroll
                for (int nt = 0; nt < 4; nt++) {
                    mma_ba(acc[mt][nt], Ah, bh[nt][0], bh[nt][1]);
                    mma_ba(acc[mt][nt], Al, bh[nt][0], bh[nt][1]);
                    mma_ba(acc[mt][nt], Ah, bl[nt][0], bl[nt][1]);
                }
            }
        }
        __syncthreads();
    }

#pragma unroll
    for (int mt = 0; mt < 9; mt++) {
#pragma unroll
        for (int nt = 0; nt < 4; nt++) {
            int px = pq * 32 + nt * 8 + 2 * t4;
#pragma unroll
            for (int r = 0; r < 2; r++) {
                int o = oh * 144 + mt * 16 + r4 + 8 * r;
                float bias = d_ball[o];
                float va = acc[mt][nt][2 * r]     + bias;
                float vb = acc[mt][nt][2 * r + 1] + bias;
                if (oh == 0 && mt == 0) {
                    size_t base = ((size_t)b * HW_ + px0 + px) * 32;
                    float ha = bfv(va), hb = bfv(vb);
                    d_fkm[base + o]      = __float2bfloat16(ha);
                    d_fkm[base + 16 + o] = __float2bfloat16(va - ha);
                    d_fkm[base + 32 + o] = __float2bfloat16(hb);
                    d_fkm[base + 48 + o] = __float2bfloat16(vb - hb);
                } else if (oh == 0 && mt == 1) {
                    float2 st; st.x = va; st.y = vb;
                    *(float2*)&d_gbuf[((size_t)b * DQK + (o - 16)) * HW_ + px0 + px] = st;
                } else {
                    int c = o - 32;
                    int pxp = (px & ~15) | kperm(px & 15);
                    *(uint32_t*)&d_hh[((size_t)b * CIN + c) * HW_ + px0 + pxp] = pack_h2(va, vb);
                }
            }
        }
    }
}

// ---------------- attention: round-10 structure (128q CTA, 512 thr) + batched prepass ----------------
// 16 warps = 4 qgroups x 4 subs. QK: 16 keys/warp. PV: 32q x 64ch/warp.
#define FROW 80
#define FSZ  5120
#define VROW 160
#define VSZ  40960
#define PROW 160
#define PSZ  20480
#define OFF_F 0
#define OFF_V 15360
#define OFF_P 138240
#define OFF_RS 179200
#define SMEM_BYTES (179200 + 2048)
// prepass: 4 slots of 2 tiles (F-hi only) carved from the P region
#define PPSLOT 10240   // 2 tiles x 5120

__device__ __forceinline__ void load_tile(uint32_t sb, int slot,
                                          const __nv_bfloat16* fkm, const __half* vb,
                                          int m0, int tid) {
    if (tid < 256) {
        int key = tid >> 2, g = tid & 3;
        CP16(sb + OFF_F + slot * FSZ + key * FROW + g * 16, fkm + (size_t)(m0 + key) * 32 + g * 8);
    }
    uint32_t vdst = sb + OFF_V + slot * VSZ;
#pragma unroll
    for (int j = 0; j < 4; j++) {
        int i = tid + 512 * j;
        int row = i >> 3, c = i & 7;
        CP16(vdst + row * VROW + c * 16, vb + (size_t)row * HW_ + m0 + c * 8);
    }
    CP_COMMIT();
}

// prepass: load 2 tiles' F-hi planes into slot blk&3 of the P region
__device__ __forceinline__ void load_fp2(uint32_t sb, int blk, const __nv_bfloat16* fkm, int tid) {
    if (blk < 32 && tid < 256) {
        int t   = tid >> 7;          // 0..1 (which tile of the pair)
        int key = (tid & 127) >> 1;  // 0..63
        int g   = tid & 1;
        CP16(sb + OFF_P + (blk & 3) * PPSLOT + t * FSZ + key * FROW + g * 16,
             fkm + (size_t)((2 * blk + t) * 64 + key) * 32 + g * 8);
    }
    CP_COMMIT();   // always commit — keeps wait_group invariant at the tail
}

// QK (bf16 x3, 16 keys) + softmax + P store
__device__ __forceinline__ void qk_tile(uint32_t sb, int fslot, int pslot,
                                        const uint32_t qh[2][4], const uint32_t ql[2][4],
                                        const float negml[2][2], float rs[2][2],
                                        int sub, int t4, int r4, int qbase) {
    const uint32_t fb_ = sb + OFF_F + fslot * FSZ + (sub * 16 + r4) * FROW + t4 * 4;
    float s[2][2][4];
#pragma unroll
    for (int nt = 0; nt < 2; nt++) {
        uint32_t ar = fb_ + nt * 8 * FROW;
        uint32_t bh0 = lds32(ar), bh1 = lds32(ar + 16);
        uint32_t bl0 = lds32(ar + 32), bl1 = lds32(ar + 48);
        mma_bz(s[0][nt], qh[0], bh0, bh1);
        mma_bz(s[1][nt], qh[1], bh0, bh1);
        mma_ba(s[0][nt], ql[0], bh0, bh1);
        mma_ba(s[1][nt], ql[1], bh0, bh1);
        mma_ba(s[0][nt], qh[0], bl0, bl1);
        mma_ba(s[1][nt], qh[1], bl0, bl1);
    }
    const uint32_t pbase = sb + OFF_P + pslot * PSZ + qbase * PROW;
    const uint32_t poff = sub * 32 + t4 * 8;
#pragma unroll
    for (int qt = 0; qt < 2; qt++) {
        uint32_t prow = pbase + (qt * 16 + r4) * PROW;
#pragma unroll
        for (int nt = 0; nt < 2; nt++) {
            float pa0 = ex2(fmaf(s[qt][nt][0], L2E, negml[qt][0]));
            float pa1 = ex2(fmaf(s[qt][nt][1], L2E, negml[qt][0]));
            float pb0 = ex2(fmaf(s[qt][nt][2], L2E, negml[qt][1]));
            float pb1 = ex2(fmaf(s[qt][nt][3], L2E, negml[qt][1]));
            rs[qt][0] += pa0 + pa1;
            rs[qt][1] += pb0 + pb1;
            uint32_t off = poff + nt * 4;
            sts32(prow + off, pack_h2(pa0, pa1));
            sts32(prow + 8 * PROW + off, pack_h2(pb0, pb1));
        }
    }
}

// PV (fp16): 32 queries x 64 channels per warp
__device__ __forceinline__ void pv_tile(uint32_t sb, int vslot, int pslot,
                                        float acc0[8][4], float acc1[8][4],
                                        int sub, int t4, int r4, int qbase) {
    const uint32_t pbase = sb + OFF_P + pslot * PSZ + qbase * PROW;
    const uint32_t vrow = sb + OFF_V + vslot * VSZ + (sub * 64 + r4) * VROW + t4 * 8;
#pragma unroll
    for (int ks = 0; ks < 4; ks++) {
        uint32_t A0[4], A1[4];
        uint32_t pr = pbase + r4 * PROW + ks * 32 + t4 * 8;
        lds64(A0[0], A0[2], pr);
        lds64(A0[1], A0[3], pr + 8 * PROW);
        lds64(A1[0], A1[2], pr + 16 * PROW);
        lds64(A1[1], A1[3], pr + 24 * PROW);
        const uint32_t vk = vrow + ks * 32;
#pragma unroll
        for (int ct = 0; ct < 8; ct++) {
            uint32_t b0, b1;
            lds64(b0, b1, vk + ct * 8 * VROW);
            mma_h16(acc0[ct], A0, b0, b1);
            mma_h16(acc1[ct], A1, b0, b1);
        }
    }
}

__global__ __launch_bounds__(512, 1) void attn_kernel(const float* __restrict__ x,
                                                      const float* __restrict__ gamma_p,
                                                      float* __restrict__ out) {
    extern __shared__ char smraw[];
    const uint32_t sb = smem_u32(smraw);
    float* rsm = (float*)(smraw + OFF_RS);
    const int tid = threadIdx.x, wid = tid >> 5, lane = tid & 31;
    const int t4 = lane & 3, r4 = lane >> 2;
    const int qg = wid >> 2, sub = wid & 3;
    const int qbase = qg * 32;
    const int b = blockIdx.y, n0 = blockIdx.x * 128;

    const float*         gb  = d_gbuf + (size_t)b * DQK * HW_;
    const __nv_bfloat16* fkm = d_fkm + (size_t)b * HW_ * 32;
    const __half*        vbp = d_hh  + (size_t)b * CIN * HW_;

    // ---- Q fragments: bf16 hi/lo ----
    uint32_t qh[2][4], ql[2][4];
#pragma unroll
    for (int qt = 0; qt < 2; qt++) {
        const int nq = n0 + qbase + qt * 16 + r4;
#pragma unroll
        for (int h = 0; h < 2; h++) {
            int k0 = 2 * t4 + 8 * h;
            float va0 = gb[(size_t)k0 * HW_ + nq];
            float va1 = gb[(size_t)(k0 + 1) * HW_ + nq];
            float vb0 = gb[(size_t)k0 * HW_ + nq + 8];
            float vb1 = gb[(size_t)(k0 + 1) * HW_ + nq + 8];
            float ha0 = bfv(va0), ha1 = bfv(va1), hb0 = bfv(vb0), hb1 = bfv(vb1);
            qh[qt][2 * h]     = pack_b2(ha0, ha1);
            qh[qt][2 * h + 1] = pack_b2(hb0, hb1);
            ql[qt][2 * h]     = pack_b2(va0 - ha0, va1 - ha1);
            ql[qt][2 * h + 1] = pack_b2(vb0 - hb0, vb1 - hb1);
        }
    }

    // ====== PREPASS: exact per-row max, BATCHED 2 tiles per sync (32 blocks) ======
    // 4 slots in the P region; prefetch depth 3 (wait_group 2). Every block issues
    // a commit group (possibly empty) so the group-count invariant holds at the tail.
    float smax[2][2] = {{-1e30f, -1e30f}, {-1e30f, -1e30f}};
    load_fp2(sb, 0, fkm, tid);
    load_fp2(sb, 1, fkm, tid);
    load_fp2(sb, 2, fkm, tid);
    for (int blk = 0; blk < 32; blk++) {
        CP_WAIT2();
        __syncthreads();                        // slot blk&3 ready; slot (blk-1)&3 fully read
        load_fp2(sb, blk + 3, fkm, tid);        // writes slot (blk+3)&3 == (blk-1)&3
#pragma unroll
        for (int t = 0; t < 2; t++) {
            const uint32_t fb_ = sb + OFF_P + (blk & 3) * PPSLOT + t * FSZ
                                 + (sub * 16 + r4) * FROW + t4 * 4;
#pragma unroll
            for (int nt = 0; nt < 2; nt++) {
                uint32_t ar = fb_ + nt * 8 * FROW;
                uint32_t b0 = lds32(ar), b1 = lds32(ar + 16);
                float s0[4], s1[4];
                mma_bz(s0, qh[0], b0, b1);
                mma_bz(s1, qh[1], b0, b1);
                smax[0][0] = fmaxf(smax[0][0], fmaxf(s0[0], s0[1]));
                smax[0][1] = fmaxf(smax[0][1], fmaxf(s0[2], s0[3]));
                smax[1][0] = fmaxf(smax[1][0], fmaxf(s1[0], s1[1]));
                smax[1][1] = fmaxf(smax[1][1], fmaxf(s1[2], s1[3]));
            }
        }
    }
    CP_WAIT0();
#pragma unroll
    for (int qt = 0; qt < 2; qt++)
#pragma unroll
        for (int j = 0; j < 2; j++) {
            float m = smax[qt][j];
            m = fmaxf(m, __shfl_xor_sync(0xffffffffu, m, 1));
            m = fmaxf(m, __shfl_xor_sync(0xffffffffu, m, 2));
            smax[qt][j] = m;
        }
    __syncthreads();
    if (t4 == 0) {
#pragma unroll
        for (int qt = 0; qt < 2; qt++) {
            rsm[sub * 128 + qbase + qt * 16 + r4]     = smax[qt][0];
            rsm[sub * 128 + qbase + qt * 16 + r4 + 8] = smax[qt][1];
        }
    }
    __syncthreads();
    float negml[2][2];
#pragma unroll
    for (int qt = 0; qt < 2; qt++) {
#pragma unroll
        for (int j = 0; j < 2; j++) {
            int row = qbase + qt * 16 + r4 + 8 * j;
            float m = fmaxf(fmaxf(rsm[row], rsm[128 + row]),
                            fmaxf(rsm[256 + row], rsm[384 + row]));
            negml[qt][j] = PSHIFT - m * L2E;
        }
    }
    __syncthreads();   // P region free for reuse

    // ================= MAIN LOOP (round-10 structure) =================
    float acc0[8][4], acc1[8][4];
#pragma unroll
    for (int ct = 0; ct < 8; ct++) {
        acc0[ct][0] = acc0[ct][1] = acc0[ct][2] = acc0[ct][3] = 0.f;
        acc1[ct][0] = acc1[ct][1] = acc1[ct][2] = acc1[ct][3] = 0.f;
    }
    float rs[2][2] = {{0.f, 0.f}, {0.f, 0.f}};

    load_tile(sb, 0, fkm, vbp, 0, tid);
    load_tile(sb, 1, fkm, vbp, 64, tid);
    CP_WAIT1();
    __syncthreads();
    qk_tile(sb, 0, 0, qh, ql, negml, rs, sub, t4, r4, qbase);

    for (int i = 0; i < 64; i++) {
        CP_WAIT0();
        __syncthreads();
        if (i + 2 < 64) load_tile(sb, (i + 2) % 3, fkm, vbp, (i + 2) * 64, tid);
        if (i + 1 < 64) qk_tile(sb, (i + 1) % 3, (i + 1) & 1, qh, ql, negml, rs, sub, t4, r4, qbase);
        pv_tile(sb, i % 3, i & 1, acc0, acc1, sub, t4, r4, qbase);
    }

    // ---- combine row sums across the four key-quarters ----
    __syncthreads();
#pragma unroll
    for (int qt = 0; qt < 2; qt++) {
        float r0 = rs[qt][0], r1 = rs[qt][1];
        r0 += __shfl_xor_sync(0xffffffffu, r0, 1); r0 += __shfl_xor_sync(0xffffffffu, r0, 2);
        r1 += __shfl_xor_sync(0xffffffffu, r1, 1); r1 += __shfl_xor_sync(0xffffffffu, r1, 2);
        if (t4 == 0) {
            rsm[sub * 128 + qbase + qt * 16 + r4]     = r0;
            rsm[sub * 128 + qbase + qt * 16 + r4 + 8] = r1;
        }
    }
    __syncthreads();

    // ---- epilogue ----
    const float gm = *gamma_p;
    const float* xb = x + (size_t)b * CIN * HW_;
    float* ob = out + (size_t)b * CIN * HW_;
#pragma unroll
    for (int qt = 0; qt < 2; qt++) {
        float (*acc)[4] = qt ? acc1 : acc0;
        int qa = qbase + qt * 16 + r4, qb2 = qa + 8;
        float suma = rsm[qa] + rsm[128 + qa] + rsm[256 + qa] + rsm[384 + qa];
        float sumb = rsm[qb2] + rsm[128 + qb2] + rsm[256 + qb2] + rsm[384 + qb2];
        float inva = gm / suma;
        float invb = gm / sumb;
        int na = n0 + qa, nb = n0 + qb2;
#pragma unroll
        for (int ct = 0; ct < 8; ct++) {
            int ch0 = sub * 64 + ct * 8 + 2 * t4, ch1 = ch0 + 1;
            ob[(size_t)ch0 * HW_ + na] = fmaf(inva, acc[ct][0], xb[(size_t)ch0 * HW_ + na]);
            ob[(size_t)ch1 * HW_ + na] = fmaf(inva, acc[ct][1], xb[(size_t)ch1 * HW_ + na]);
            ob[(size_t)ch0 * HW_ + nb] = fmaf(invb, acc[ct][2], xb[(size_t)ch0 * HW_ + nb]);
            ob[(size_t)ch1 * HW_ + nb] = fmaf(invb, acc[ct][3], xb[(size_t)ch1 * HW_ + nb]);
        }
    }
}

// ---------------- launch ----------------
extern "C" void kernel_launch(void* const* d_in, const int* in_sizes, int n_in,
                              void* d_out, int out_size) {
    const float* x  = (const float*)d_in[0];
    const float* Wf = (const float*)d_in[1];
    const float* bf = (const float*)d_in[2];
    const float* Wg = (const float*)d_in[3];
    const float* bg = (const float*)d_in[4];
    const float* Wh = (const float*)d_in[5];
    const float* bh = (const float*)d_in[6];
    const float* gamma = (const float*)d_in[7];
    float* out = (float*)d_out;

    prep_kernel<<<(NO_ * CIN + 255) / 256, 256>>>(Wf, bf, Wg, bg, Wh, bh);
    xconv_kernel<<<dim3(HW_ / 64, CIN / 32, B_), 256>>>(x);

    cudaFuncSetAttribute(proj_mma_kernel, cudaFuncAttributeMaxDynamicSharedMemorySize, PROJ_SMEM);
    proj_mma_kernel<<<dim3(HW_ / 128, B_), 256, PROJ_SMEM>>>();

    cudaFuncSetAttribute(attn_kernel, cudaFuncAttributeMaxDynamicSharedMemorySize, SMEM_BYTES);
    attn_kernel<<<dim3(HW_ / 128, B_), 512, SMEM_BYTES>>>(x, gamma, out);
}

// round 14
// speedup vs baseline: 1.6478x; 1.0018x over previous
#include <cuda_runtime.h>
#include <cuda_bf16.h>
#include <cuda_fp16.h>
#include <cstdint>

#define B_   8
#define CIN  256
#define HW_  4096
#define DQK  16
#define NO_  288
#define L2E  1.4426950408889634f
#define PSHIFT 10.0f

typedef unsigned long long u64;

// ---------------- portable PTX helpers ----------------
__device__ __forceinline__ uint32_t smem_u32(const void* p) {
    uint32_t a;
    asm("{ .reg .u64 t; cvta.to.shared.u64 t, %1; cvt.u32.u64 %0, t; }" : "=r"(a) : "l"(p));
    return a;
}
__device__ __forceinline__ float ex2(float v) {
    float r; asm("ex2.approx.f32 %0, %1;" : "=f"(r) : "f"(v)); return r;
}
__device__ __forceinline__ uint32_t pack_h2(float lo, float hi) {
    uint32_t d; asm("cvt.rn.f16x2.f32 %0, %1, %2;" : "=r"(d) : "f"(hi), "f"(lo)); return d;
}
__device__ __forceinline__ uint32_t pack_b2(float lo, float hi) {
    uint32_t d; asm("cvt.rn.bf16x2.f32 %0, %1, %2;" : "=r"(d) : "f"(hi), "f"(lo)); return d;
}
__device__ __forceinline__ float bfv(float v) {
    __nv_bfloat16 h = __float2bfloat16(v);
    return __bfloat162float(h);
}
__device__ __forceinline__ uint32_t lds32(uint32_t a) {
    uint32_t v; asm volatile("ld.shared.b32 %0, [%1];" : "=r"(v) : "r"(a)); return v;
}
__device__ __forceinline__ void lds64(uint32_t& x, uint32_t& y, uint32_t a) {
    asm volatile("ld.shared.v2.b32 {%0, %1}, [%2];" : "=r"(x), "=r"(y) : "r"(a));
}
__device__ __forceinline__ void sts32(uint32_t a, uint32_t v) {
    asm volatile("st.shared.b32 [%0], %1;" :: "r"(a), "r"(v));
}
#define CP16(dst, src) asm volatile("cp.async.cg.shared.global [%0], [%1], 16;" :: "r"(dst), "l"(src))
#define CP_COMMIT()    asm volatile("cp.async.commit_group;" ::: "memory")
#define CP_WAIT0()     asm volatile("cp.async.wait_group 0;" ::: "memory")
#define CP_WAIT1()     asm volatile("cp.async.wait_group 1;" ::: "memory")
#define CP_WAIT2()     asm volatile("cp.async.wait_group 2;" ::: "memory")

// bf16 m16n8k16 (fp32 accum)
__device__ __forceinline__ void mma_ba(float* d, const uint32_t* a, uint32_t b0, uint32_t b1) {
    asm volatile("mma.sync.aligned.m16n8k16.row.col.f32.bf16.bf16.f32 "
        "{%0,%1,%2,%3}, {%4,%5,%6,%7}, {%8,%9}, {%0,%1,%2,%3};"
        : "+f"(d[0]), "+f"(d[1]), "+f"(d[2]), "+f"(d[3])
        : "r"(a[0]), "r"(a[1]), "r"(a[2]), "r"(a[3]), "r"(b0), "r"(b1));
}
__device__ __forceinline__ void mma_bz(float* d, const uint32_t* a, uint32_t b0, uint32_t b1) {
    float z = 0.f;
    asm volatile("mma.sync.aligned.m16n8k16.row.col.f32.bf16.bf16.f32 "
        "{%0,%1,%2,%3}, {%4,%5,%6,%7}, {%8,%9}, {%10,%10,%10,%10};"
        : "=f"(d[0]), "=f"(d[1]), "=f"(d[2]), "=f"(d[3])
        : "r"(a[0]), "r"(a[1]), "r"(a[2]), "r"(a[3]), "r"(b0), "r"(b1), "f"(z));
}
// fp16 m16n8k16 (fp32 accum)
__device__ __forceinline__ void mma_h16(float* d, const uint32_t* a, uint32_t b0, uint32_t b1) {
    asm volatile("mma.sync.aligned.m16n8k16.row.col.f32.f16.f16.f32 "
        "{%0,%1,%2,%3}, {%4,%5,%6,%7}, {%8,%9}, {%0,%1,%2,%3};"
        : "+f"(d[0]), "+f"(d[1]), "+f"(d[2]), "+f"(d[3])
        : "r"(a[0]), "r"(a[1]), "r"(a[2]), "r"(a[3]), "r"(b0), "r"(b1));
}

// key permutation within 16-groups (pairs stay adjacent)
__device__ __forceinline__ int kperm(int e) {
    return (((e & 7) >> 1) << 2) | (e & 1) | ((e >> 3) << 1);
}

// ---------------- scratch ----------------
__device__ float         d_gbuf[B_ * DQK * HW_];
__device__ __nv_bfloat16 d_fkm[(size_t)B_ * HW_ * 32];   // F key-major: 16 hi + 16 lo bf16
__device__ __half        d_hh[(size_t)B_ * CIN * HW_];   // V fp16, key-permuted within 16-groups
__device__ __nv_bfloat16 d_xt[(size_t)B_ * HW_ * 512];   // x pixel-major: [b][px][plane][c]
__device__ __nv_bfloat16 d_wt[NO_ * 512];                // W: [o][plane][c]
__device__ float         d_ball[NO_];

// ---------------- prep ----------------
__global__ void prep_kernel(const float* __restrict__ Wf, const float* __restrict__ bf,
                            const float* __restrict__ Wg, const float* __restrict__ bg,
                            const float* __restrict__ Wh, const float* __restrict__ bh) {
    int i = blockIdx.x * blockDim.x + threadIdx.x;
    if (i >= NO_ * CIN) return;
    int o = i >> 8, c = i & 255;
    float w = (o < 16) ? Wf[o * 256 + c] : ((o < 32) ? Wg[(o - 16) * 256 + c] : Wh[(o - 32) * 256 + c]);
    float h = bfv(w);
    d_wt[o * 512 + c]       = __float2bfloat16(h);
    d_wt[o * 512 + 256 + c] = __float2bfloat16(w - h);
    if (c == 0) d_ball[o] = (o < 16) ? bf[o] : ((o < 32) ? bg[o - 16] : bh[o - 32]);
}

// ---------------- xconv ----------------
__global__ __launch_bounds__(256) void xconv_kernel(const float* __restrict__ x) {
    __shared__ float tx[32][65];
    const int px0 = blockIdx.x * 64;
    const int c0  = blockIdx.y * 32;
    const int b   = blockIdx.z;
    const int tid = threadIdx.x;
    const float* xb = x + (size_t)b * CIN * HW_;
#pragma unroll
    for (int it = 0; it < 8; it++) {
        int e = tid + 256 * it;
        int c = e >> 6, p = e & 63;
        tx[c][p] = xb[(size_t)(c0 + c) * HW_ + px0 + p];
    }
    __syncthreads();
    uint32_t* dst = (uint32_t*)d_xt;
#pragma unroll
    for (int it = 0; it < 8; it++) {
        int e = tid + 256 * it;
        int px = e >> 5, q = e & 31;
        int plane = q >> 4, cp = q & 15;
        float v0 = tx[2 * cp][px], v1 = tx[2 * cp + 1][px];
        float h0 = bfv(v0), h1 = bfv(v1);
        uint32_t outw = plane ? pack_b2(v0 - h0, v1 - h1) : pack_b2(h0, h1);
        size_t idx = (((size_t)b * HW_ + px0 + px) * 512 + plane * 256 + c0 + 2 * cp) >> 1;
        dst[idx] = outw;
    }
}

// ---------------- proj GEMM on tensor cores (bf16 x3) ----------------
#define PX_STRIDE 144
#define PW_STRIDE 144
#define PX_SZ     (128 * PX_STRIDE)
#define PW_OFF    (2 * PX_SZ)
#define PW_SZ     (288 * PW_STRIDE)
#define PROJ_SMEM (PW_OFF + 2 * PW_SZ)

__device__ __forceinline__ void proj_load(uint32_t sb, int slot, int b, int px0, int kc, int tid) {
    uint32_t xdst = sb + slot * PX_SZ;
    const __nv_bfloat16* xsrc = d_xt + ((size_t)b * HW_ + px0) * 512 + kc;
#pragma unroll
    for (int j = 0; j < 4; j++) {
        int e = tid * 4 + j;
        int px = e >> 3, sub = e & 7;
        int pl = sub >> 2, c16 = sub & 3;
        CP16(xdst + px * PX_STRIDE + pl * 64 + c16 * 16, xsrc + (size_t)px * 512 + pl * 256 + c16 * 8);
    }
    uint32_t wdst = sb + PW_OFF + slot * PW_SZ;
    const __nv_bfloat16* wsrc = d_wt + kc;
#pragma unroll
    for (int it = 0; it < 9; it++) {
        int e = tid + 256 * it;
        int o = e >> 3, sub = e & 7;
        int pl = sub >> 2, c16 = sub & 3;
        CP16(wdst + o * PW_STRIDE + pl * 64 + c16 * 16, wsrc + (size_t)o * 512 + pl * 256 + c16 * 8);
    }
    CP_COMMIT();
}

__global__ __launch_bounds__(256, 1) void proj_mma_kernel() {
    extern __shared__ char smraw[];
    const uint32_t sb = smem_u32(smraw);
    const int tid = threadIdx.x, wid = tid >> 5, lane = tid & 31;
    const int t4 = lane & 3, r4 = lane >> 2;
    const int oh = wid & 1, pq = wid >> 1;
    const int px0 = blockIdx.x * 128;
    const int b = blockIdx.y;

    float acc[9][4][4];
#pragma unroll
    for (int mt = 0; mt < 9; mt++)
#pragma unroll
        for (int nt = 0; nt < 4; nt++) { acc[mt][nt][0] = acc[mt][nt][1] = acc[mt][nt][2] = acc[mt][nt][3] = 0.f; }

    proj_load(sb, 0, b, px0, 0, tid);

    for (int ch = 0; ch < 8; ch++) {
        CP_WAIT0();
        __syncthreads();
        if (ch + 1 < 8) proj_load(sb, (ch + 1) & 1, b, px0, (ch + 1) * 32, tid);

        const uint32_t xs = sb + (ch & 1) * PX_SZ;
        const uint32_t ws = sb + PW_OFF + (ch & 1) * PW_SZ;
#pragma unroll
        for (int ks = 0; ks < 2; ks++) {
            uint32_t bh[4][2], bl[4][2];
#pragma unroll
            for (int nt = 0; nt < 4; nt++) {
                uint32_t base = xs + (pq * 32 + nt * 8 + r4) * PX_STRIDE + ks * 32 + t4 * 4;
                bh[nt][0] = lds32(base);       bh[nt][1] = lds32(base + 16);
                bl[nt][0] = lds32(base + 64);  bl[nt][1] = lds32(base + 80);
            }
#pragma unroll
            for (int mt = 0; mt < 9; mt++) {
                uint32_t base = ws + (oh * 144 + mt * 16 + r4) * PW_STRIDE + ks * 32 + t4 * 4;
                uint32_t Ah[4], Al[4];
                Ah[0] = lds32(base);                 Ah[1] = lds32(base + 8 * PW_STRIDE);
                Ah[2] = lds32(base + 16);            Ah[3] = lds32(base + 8 * PW_STRIDE + 16);
                Al[0] = lds32(base + 64);            Al[1] = lds32(base + 8 * PW_STRIDE + 64);
                Al[2] = lds32(base + 80);            Al[3] = lds32(base + 8 * PW_STRIDE + 80);
#pragma unroll
                for (int nt = 0; nt < 4; nt++) {
                    mma_ba(acc[mt][nt], Ah, bh[nt][0], bh[nt][1]);
                    mma_ba(acc[mt][nt], Al, bh[nt][0], bh[nt][1]);
                    mma_ba(acc[mt][nt], Ah, bl[nt][0], bl[nt][1]);
                }
            }
        }
        __syncthreads();
    }

#pragma unroll
    for (int mt = 0; mt < 9; mt++) {
#pragma unroll
        for (int nt = 0; nt < 4; nt++) {
            int px = pq * 32 + nt * 8 + 2 * t4;
#pragma unroll
            for (int r = 0; r < 2; r++) {
                int o = oh * 144 + mt * 16 + r4 + 8 * r;
                float bias = d_ball[o];
                float va = acc[mt][nt][2 * r]     + bias;
                float vb = acc[mt][nt][2 * r + 1] + bias;
                if (oh == 0 && mt == 0) {
                    size_t base = ((size_t)b * HW_ + px0 + px) * 32;
                    float ha = bfv(va), hb = bfv(vb);
                    d_fkm[base + o]      = __float2bfloat16(ha);
                    d_fkm[base + 16 + o] = __float2bfloat16(va - ha);
                    d_fkm[base + 32 + o] = __float2bfloat16(hb);
                    d_fkm[base + 48 + o] = __float2bfloat16(vb - hb);
                } else if (oh == 0 && mt == 1) {
                    float2 st; st.x = va; st.y = vb;
                    *(float2*)&d_gbuf[((size_t)b * DQK + (o - 16)) * HW_ + px0 + px] = st;
                } else {
                    int c = o - 32;
                    int pxp = (px & ~15) | kperm(px & 15);
                    *(uint32_t*)&d_hh[((size_t)b * CIN + c) * HW_ + px0 + pxp] = pack_h2(va, vb);
                }
            }
        }
    }
}

// ---------------- attention: round-10 structure (128q CTA, 512 thr) + batched prepass ----------------
// 16 warps = 4 qgroups x 4 subs. QK: 16 keys/warp. PV: 32q x 64ch/warp.
#define FROW 80
#define FSZ  5120
#define VROW 160
#define VSZ  40960
#define PROW 160
#define PSZ  20480
#define OFF_F 0
#define OFF_V 15360
#define OFF_P 138240
#define OFF_RS 179200
#define SMEM_BYTES (179200 + 2048)
// prepass: 4 slots of 2 tiles (F-hi only) carved from the P region
#define PPSLOT 10240   // 2 tiles x 5120

__device__ __forceinline__ void load_tile(uint32_t sb, int slot,
                                          const __nv_bfloat16* fkm, const __half* vb,
                                          int m0, int tid) {
    if (tid < 256) {
        int key = tid >> 2, g = tid & 3;
        CP16(sb + OFF_F + slot * FSZ + key * FROW + g * 16, fkm + (size_t)(m0 + key) * 32 + g * 8);
    }
    uint32_t vdst = sb + OFF_V + slot * VSZ;
#pragma unroll
    for (int j = 0; j < 4; j++) {
        int i = tid + 512 * j;
        int row = i >> 3, c = i & 7;
        CP16(vdst + row * VROW + c * 16, vb + (size_t)row * HW_ + m0 + c * 8);
    }
    CP_COMMIT();
}

// prepass: load 2 tiles' F-hi planes into slot blk&3 of the P region
__device__ __forceinline__ void load_fp2(uint32_t sb, int blk, const __nv_bfloat16* fkm, int tid) {
    if (blk < 32 && tid < 256) {
        int t   = tid >> 7;          // 0..1 (which tile of the pair)
        int key = (tid & 127) >> 1;  // 0..63
        int g   = tid & 1;
        CP16(sb + OFF_P + (blk & 3) * PPSLOT + t * FSZ + key * FROW + g * 16,
             fkm + (size_t)((2 * blk + t) * 64 + key) * 32 + g * 8);
    }
    CP_COMMIT();   // always commit — keeps wait_group invariant at the tail
}

// QK (bf16 x3, 16 keys) + softmax + P store
__device__ __forceinline__ void qk_tile(uint32_t sb, int fslot, int pslot,
                                        const uint32_t qh[2][4], const uint32_t ql[2][4],
                                        const float negml[2][2], float rs[2][2],
                                        int sub, int t4, int r4, int qbase) {
    const uint32_t fb_ = sb + OFF_F + fslot * FSZ + (sub * 16 + r4) * FROW + t4 * 4;
    float s[2][2][4];
#pragma unroll
    for (int nt = 0; nt < 2; nt++) {
        uint32_t ar = fb_ + nt * 8 * FROW;
        uint32_t bh0 = lds32(ar), bh1 = lds32(ar + 16);
        uint32_t bl0 = lds32(ar + 32), bl1 = lds32(ar + 48);
        mma_bz(s[0][nt], qh[0], bh0, bh1);
        mma_bz(s[1][nt], qh[1], bh0, bh1);
        mma_ba(s[0][nt], ql[0], bh0, bh1);
        mma_ba(s[1][nt], ql[1], bh0, bh1);
        mma_ba(s[0][nt], qh[0], bl0, bl1);
        mma_ba(s[1][nt], qh[1], bl0, bl1);
    }
    const uint32_t pbase = sb + OFF_P + pslot * PSZ + qbase * PROW;
    const uint32_t poff = sub * 32 + t4 * 8;
#pragma unroll
    for (int qt = 0; qt < 2; qt++) {
        uint32_t prow = pbase + (qt * 16 + r4) * PROW;
#pragma unroll
        for (int nt = 0; nt < 2; nt++) {
            float pa0 = ex2(fmaf(s[qt][nt][0], L2E, negml[qt][0]));
            float pa1 = ex2(fmaf(s[qt][nt][1], L2E, negml[qt][0]));
            float pb0 = ex2(fmaf(s[qt][nt][2], L2E, negml[qt][1]));
            float pb1 = ex2(fmaf(s[qt][nt][3], L2E, negml[qt][1]));
            rs[qt][0] += pa0 + pa1;
            rs[qt][1] += pb0 + pb1;
            uint32_t off = poff + nt * 4;
            sts32(prow + off, pack_h2(pa0, pa1));
            sts32(prow + 8 * PROW + off, pack_h2(pb0, pb1));
        }
    }
}

// PV (fp16): 32 queries x 64 channels per warp
__device__ __forceinline__ void pv_tile(uint32_t sb, int vslot, int pslot,
                                        float acc0[8][4], float acc1[8][4],
                                        int sub, int t4, int r4, int qbase) {
    const uint32_t pbase = sb + OFF_P + pslot * PSZ + qbase * PROW;
    const uint32_t vrow = sb + OFF_V + vslot * VSZ + (sub * 64 + r4) * VROW + t4 * 8;
#pragma unroll
    for (int ks = 0; ks < 4; ks++) {
        uint32_t A0[4], A1[4];
        uint32_t pr = pbase + r4 * PROW + ks * 32 + t4 * 8;
        lds64(A0[0], A0[2], pr);
        lds64(A0[1], A0[3], pr + 8 * PROW);
        lds64(A1[0], A1[2], pr + 16 * PROW);
        lds64(A1[1], A1[3], pr + 24 * PROW);
        const uint32_t vk = vrow + ks * 32;
#pragma unroll
        for (int ct = 0; ct < 8; ct++) {
            uint32_t b0, b1;
            lds64(b0, b1, vk + ct * 8 * VROW);
            mma_h16(acc0[ct], A0, b0, b1);
            mma_h16(acc1[ct], A1, b0, b1);
        }
    }
}

__global__ __launch_bounds__(512, 1) void attn_kernel(const float* __restrict__ x,
                                                      const float* __restrict__ gamma_p,
                                                      float* __restrict__ out) {
    extern __shared__ char smraw[];
    const uint32_t sb = smem_u32(smraw);
    float* rsm = (float*)(smraw + OFF_RS);
    const int tid = threadIdx.x, wid = tid >> 5, lane = tid & 31;
    const int t4 = lane & 3, r4 = lane >> 2;
    const int qg = wid >> 2, sub = wid & 3;
    const int qbase = qg * 32;
    const int b = blockIdx.y, n0 = blockIdx.x * 128;

    const float*         gb  = d_gbuf + (size_t)b * DQK * HW_;
    const __nv_bfloat16* fkm = d_fkm + (size_t)b * HW_ * 32;
    const __half*        vbp = d_hh  + (size_t)b * CIN * HW_;

    // ---- Q fragments: bf16 hi/lo ----
    uint32_t qh[2][4], ql[2][4];
#pragma unroll
    for (int qt = 0; qt < 2; qt++) {
        const int nq = n0 + qbase + qt * 16 + r4;
#pragma unroll
        for (int h = 0; h < 2; h++) {
            int k0 = 2 * t4 + 8 * h;
            float va0 = gb[(size_t)k0 * HW_ + nq];
            float va1 = gb[(size_t)(k0 + 1) * HW_ + nq];
            float vb0 = gb[(size_t)k0 * HW_ + nq + 8];
            float vb1 = gb[(size_t)(k0 + 1) * HW_ + nq + 8];
            float ha0 = bfv(va0), ha1 = bfv(va1), hb0 = bfv(vb0), hb1 = bfv(vb1);
            qh[qt][2 * h]     = pack_b2(ha0, ha1);
            qh[qt][2 * h + 1] = pack_b2(hb0, hb1);
            ql[qt][2 * h]     = pack_b2(va0 - ha0, va1 - ha1);
            ql[qt][2 * h + 1] = pack_b2(vb0 - hb0, vb1 - hb1);
        }
    }

    // ====== PREPASS: exact per-row max, BATCHED 2 tiles per sync (32 blocks) ======
    // 4 slots in the P region; prefetch depth 3 (wait_group 2). Every block issues
    // a commit group (possibly empty) so the group-count invariant holds at the tail.
    float smax[2][2] = {{-1e30f, -1e30f}, {-1e30f, -1e30f}};
    load_fp2(sb, 0, fkm, tid);
    load_fp2(sb, 1, fkm, tid);
    load_fp2(sb, 2, fkm, tid);
    for (int blk = 0; blk < 32; blk++) {
        CP_WAIT2();
        __syncthreads();                        // slot blk&3 ready; slot (blk-1)&3 fully read
        load_fp2(sb, blk + 3, fkm, tid);        // writes slot (blk+3)&3 == (blk-1)&3
#pragma unroll
        for (int t = 0; t < 2; t++) {
            const uint32_t fb_ = sb + OFF_P + (blk & 3) * PPSLOT + t * FSZ
                                 + (sub * 16 + r4) * FROW + t4 * 4;
#pragma unroll
            for (int nt = 0; nt < 2; nt++) {
                uint32_t ar = fb_ + nt * 8 * FROW;
                uint32_t b0 = lds32(ar), b1 = lds32(ar + 16);
                float s0[4], s1[4];
                mma_bz(s0, qh[0], b0, b1);
                mma_bz(s1, qh[1], b0, b1);
                smax[0][0] = fmaxf(smax[0][0], fmaxf(s0[0], s0[1]));
                smax[0][1] = fmaxf(smax[0][1], fmaxf(s0[2], s0[3]));
                smax[1][0] = fmaxf(smax[1][0], fmaxf(s1[0], s1[1]));
                smax[1][1] = fmaxf(smax[1][1], fmaxf(s1[2], s1[3]));
            }
        }
    }
    CP_WAIT0();
#pragma unroll
    for (int qt = 0; qt < 2; qt++)
#pragma unroll
        for (int j = 0; j < 2; j++) {
            float m = smax[qt][j];
            m = fmaxf(m, __shfl_xor_sync(0xffffffffu, m, 1));
            m = fmaxf(m, __shfl_xor_sync(0xffffffffu, m, 2));
            smax[qt][j] = m;
        }
    __syncthreads();
    if (t4 == 0) {
#pragma unroll
        for (int qt = 0; qt < 2; qt++) {
            rsm[sub * 128 + qbase + qt * 16 + r4]     = smax[qt][0];
            rsm[sub * 128 + qbase + qt * 16 + r4 + 8] = smax[qt][1];
        }
    }
    __syncthreads();
    float negml[2][2];
#pragma unroll
    for (int qt = 0; qt < 2; qt++) {
#pragma unroll
        for (int j = 0; j < 2; j++) {
            int row = qbase + qt * 16 + r4 + 8 * j;
            float m = fmaxf(fmaxf(rsm[row], rsm[128 + row]),
                            fmaxf(rsm[256 + row], rsm[384 + row]));
            negml[qt][j] = PSHIFT - m * L2E;
        }
    }
    __syncthreads();   // P region free for reuse

    // ================= MAIN LOOP (round-10 structure) =================
    float acc0[8][4], acc1[8][4];
#pragma unroll
    for (int ct = 0; ct < 8; ct++) {
        acc0[ct][0] = acc0[ct][1] = acc0[ct][2] = acc0[ct][3] = 0.f;
        acc1[ct][0] = acc1[ct][1] = acc1[ct][2] = acc1[ct][3] = 0.f;
    }
    float rs[2][2] = {{0.f, 0.f}, {0.f, 0.f}};

    load_tile(sb, 0, fkm, vbp, 0, tid);
    load_tile(sb, 1, fkm, vbp, 64, tid);
    CP_WAIT1();
    __syncthreads();
    qk_tile(sb, 0, 0, qh, ql, negml, rs, sub, t4, r4, qbase);

    for (int i = 0; i < 64; i++) {
        CP_WAIT0();
        __syncthreads();
        if (i + 2 < 64) load_tile(sb, (i + 2) % 3, fkm, vbp, (i + 2) * 64, tid);
        if (i + 1 < 64) qk_tile(sb, (i + 1) % 3, (i + 1) & 1, qh, ql, negml, rs, sub, t4, r4, qbase);
        pv_tile(sb, i % 3, i & 1, acc0, acc1, sub, t4, r4, qbase);
    }

    // ---- combine row sums across the four key-quarters ----
    __syncthreads();
#pragma unroll
    for (int qt = 0; qt < 2; qt++) {
        float r0 = rs[qt][0], r1 = rs[qt][1];
        r0 += __shfl_xor_sync(0xffffffffu, r0, 1); r0 += __shfl_xor_sync(0xffffffffu, r0, 2);
        r1 += __shfl_xor_sync(0xffffffffu, r1, 1); r1 += __shfl_xor_sync(0xffffffffu, r1, 2);
        if (t4 == 0) {
            rsm[sub * 128 + qbase + qt * 16 + r4]     = r0;
            rsm[sub * 128 + qbase + qt * 16 + r4 + 8] = r1;
        }
    }
    __syncthreads();

    // ---- epilogue ----
    const float gm = *gamma_p;
    const float* xb = x + (size_t)b * CIN * HW_;
    float* ob = out + (size_t)b * CIN * HW_;
#pragma unroll
    for (int qt = 0; qt < 2; qt++) {
        float (*acc)[4] = qt ? acc1 : acc0;
        int qa = qbase + qt * 16 + r4, qb2 = qa + 8;
        float suma = rsm[qa] + rsm[128 + qa] + rsm[256 + qa] + rsm[384 + qa];
        float sumb = rsm[qb2] + rsm[128 + qb2] + rsm[256 + qb2] + rsm[384 + qb2];
        float inva = gm / suma;
        float invb = gm / sumb;
        int na = n0 + qa, nb = n0 + qb2;
#pragma unroll
        for (int ct = 0; ct < 8; ct++) {
            int ch0 = sub * 64 + ct * 8 + 2 * t4, ch1 = ch0 + 1;
            ob[(size_t)ch0 * HW_ + na] = fmaf(inva, acc[ct][0], xb[(size_t)ch0 * HW_ + na]);
            ob[(size_t)ch1 * HW_ + na] = fmaf(inva, acc[ct][1], xb[(size_t)ch1 * HW_ + na]);
            ob[(size_t)ch0 * HW_ + nb] = fmaf(invb, acc[ct][2], xb[(size_t)ch0 * HW_ + nb]);
            ob[(size_t)ch1 * HW_ + nb] = fmaf(invb, acc[ct][3], xb[(size_t)ch1 * HW_ + nb]);
        }
    }
}

// ---------------- launch ----------------
extern "C" void kernel_launch(void* const* d_in, const int* in_sizes, int n_in,
                              void* d_out, int out_size) {
    const float* x  = (const float*)d_in[0];
    const float* Wf = (const float*)d_in[1];
    const float* bf = (const float*)d_in[2];
    const float* Wg = (const float*)d_in[3];
    const float* bg = (const float*)d_in[4];
    const float* Wh = (const float*)d_in[5];
    const float* bh = (const float*)d_in[6];
    const float* gamma = (const float*)d_in[7];
    float* out = (float*)d_out;

    prep_kernel<<<(NO_ * CIN + 255) / 256, 256>>>(Wf, bf, Wg, bg, Wh, bh);
    xconv_kernel<<<dim3(HW_ / 64, CIN / 32, B_), 256>>>(x);

    cudaFuncSetAttribute(proj_mma_kernel, cudaFuncAttributeMaxDynamicSharedMemorySize, PROJ_SMEM);
    proj_mma_kernel<<<dim3(HW_ / 128, B_), 256, PROJ_SMEM>>>();

    cudaFuncSetAttribute(attn_kernel, cudaFuncAttributeMaxDynamicSharedMemorySize, SMEM_BYTES);
    attn_kernel<<<dim3(HW_ / 128, B_), 512, SMEM_BYTES>>>(x, gamma, out);
}